// round 8
// baseline (speedup 1.0000x reference)
#include <cuda_runtime.h>
#include <cstdint>

#define N_DIS 25000
#define N_MIR 25000
#define NN    50000
#define EE    600000
#define EMB   128
#define NB_SCAN 196   // ceil(50000/256)

#define BM 128
#define BN 128
#define BK 32
#define AST 36
#define BST 136

// ---------------- scratch (static device globals: no allocs allowed) --------
// h/h1/agg padded by one M-tile so unguarded cp.async tile reads stay in-bounds.
__device__ float g_h   [(size_t)(NN + BM) * EMB];
__device__ float g_h1  [(size_t)(NN + BM) * EMB];
__device__ float g_agg [(size_t)(NN + BM) * EMB];
__device__ float g_inv [NN];
__device__ int   g_cnt [NN];
__device__ int   g_off [NN];
__device__ int   g_cur [NN];
__device__ int   g_esrc[EE];
__device__ int   g_bsum[NB_SCAN];
__device__ float g_wl  [4 * 128 * 128];   // tf32-rounded layer weights

// ---------------- helpers ----------------------------------------------------
__device__ __forceinline__ uint32_t f2tf32(float x) {
    uint32_t r;
    asm("cvt.rna.tf32.f32 %0, %1;\n" : "=r"(r) : "f"(x));
    return r;
}
__device__ __forceinline__ float f2tf32f(float x) {
    return __uint_as_float(f2tf32(x));
}
__device__ __forceinline__ void mma_tf32(float* d, const uint32_t* a,
                                         const uint32_t* b) {
    asm volatile(
        "mma.sync.aligned.m16n8k8.row.col.f32.tf32.tf32.f32 "
        "{%0,%1,%2,%3},{%4,%5,%6,%7},{%8,%9},{%0,%1,%2,%3};\n"
        : "+f"(d[0]), "+f"(d[1]), "+f"(d[2]), "+f"(d[3])
        : "r"(a[0]), "r"(a[1]), "r"(a[2]), "r"(a[3]), "r"(b[0]), "r"(b[1]));
}
__device__ __forceinline__ void cp16(void* s, const void* g) {
    uint32_t sa = (uint32_t)__cvta_generic_to_shared(s);
    asm volatile("cp.async.cg.shared.global [%0], [%1], 16;\n"
                 :: "r"(sa), "l"(g));
}

// ---------------- CSR build --------------------------------------------------
__global__ void zero_cnt_kernel() {
    int i = blockIdx.x * blockDim.x + threadIdx.x;
    if (i < NN) g_cnt[i] = 0;
}

__global__ void count_kernel(const int* __restrict__ dst) {
    int e = blockIdx.x * blockDim.x + threadIdx.x;
    if (e < EE) atomicAdd(&g_cnt[dst[e]], 1);
}

// per-block exclusive scan of counts; block totals to g_bsum
__global__ void scan1_kernel() {
    __shared__ int sh[256];
    int t = threadIdx.x;
    int i = blockIdx.x * 256 + t;
    int v = (i < NN) ? g_cnt[i] : 0;
    sh[t] = v;
    __syncthreads();
#pragma unroll
    for (int o = 1; o < 256; o <<= 1) {
        int x = (t >= o) ? sh[t - o] : 0;
        __syncthreads();
        sh[t] += x;
        __syncthreads();
    }
    if (i < NN) g_off[i] = sh[t] - v;
    if (t == 255) g_bsum[blockIdx.x] = sh[255];
}

// fused: block b sums g_bsum[0..b-1] itself, then finalizes off/cur/inv
__global__ void scan23_kernel() {
    __shared__ int ws[8];
    int t = threadIdx.x, b = blockIdx.x;
    int v = (t < b && t < NB_SCAN) ? g_bsum[t] : 0;
#pragma unroll
    for (int o = 16; o; o >>= 1) v += __shfl_down_sync(0xffffffffu, v, o);
    if ((t & 31) == 0) ws[t >> 5] = v;
    __syncthreads();
    if (t == 0) {
        int tot = 0;
#pragma unroll
        for (int j = 0; j < 8; ++j) tot += ws[j];
        ws[0] = tot;
    }
    __syncthreads();
    int base = ws[0];
    int i = b * 256 + t;
    if (i < NN) {
        int off = g_off[i] + base;
        g_off[i] = off;
        g_cur[i] = off;
        g_inv[i] = 1.0f / fmaxf((float)g_cnt[i], 1.0f);
    }
}

__global__ void fill_kernel(const int* __restrict__ src,
                            const int* __restrict__ dst) {
    int e = blockIdx.x * blockDim.x + threadIdx.x;
    if (e >= EE) return;
    int d = dst[e];
    int pos = atomicAdd(&g_cur[d], 1);
    g_esrc[pos] = src[e];
}

// ---------------- weight pre-round (tf32) ------------------------------------
__global__ void cvtw_kernel(const float* __restrict__ W_s1,
                            const float* __restrict__ W_n1,
                            const float* __restrict__ W_s2,
                            const float* __restrict__ W_n2) {
    int i = blockIdx.x * 256 + threadIdx.x;
    if (i >= 16384) return;
    g_wl[i]             = f2tf32f(W_s1[i]);
    g_wl[16384 + i]     = f2tf32f(W_n1[i]);
    g_wl[2 * 16384 + i] = f2tf32f(W_s2[i]);
    g_wl[3 * 16384 + i] = f2tf32f(W_n2[i]);
}

// ---------------- gather-mean (stores tf32-rounded) --------------------------
__global__ void gather_kernel(const float* __restrict__ x) {
    int w    = (blockIdx.x * blockDim.x + threadIdx.x) >> 5;
    int lane = threadIdx.x & 31;
    if (w >= NN) return;
    int beg = g_off[w];
    int end = (w == NN - 1) ? EE : g_off[w + 1];

    float4 acc = make_float4(0.f, 0.f, 0.f, 0.f);
    int e = beg;
    for (; e + 1 < end; e += 2) {
        int s0 = g_esrc[e], s1 = g_esrc[e + 1];
        float4 v0 = reinterpret_cast<const float4*>(x + (size_t)s0 * EMB)[lane];
        float4 v1 = reinterpret_cast<const float4*>(x + (size_t)s1 * EMB)[lane];
        acc.x += v0.x + v1.x; acc.y += v0.y + v1.y;
        acc.z += v0.z + v1.z; acc.w += v0.w + v1.w;
    }
    if (e < end) {
        int s = g_esrc[e];
        float4 v = reinterpret_cast<const float4*>(x + (size_t)s * EMB)[lane];
        acc.x += v.x; acc.y += v.y; acc.z += v.z; acc.w += v.w;
    }
    float iv = g_inv[w];
    float4 o;
    o.x = f2tf32f(acc.x * iv); o.y = f2tf32f(acc.y * iv);
    o.z = f2tf32f(acc.z * iv); o.w = f2tf32f(acc.w * iv);
    reinterpret_cast<float4*>(g_agg + (size_t)w * EMB)[lane] = o;
}

// ---------------- shared fragment compute ------------------------------------
__device__ __forceinline__ void compute_tile(const uint32_t* __restrict__ As_,
                                             const uint32_t* __restrict__ Bs_,
                                             float acc[2][8][4],
                                             int wm, int wn, int g4, int tig) {
#pragma unroll
    for (int ks = 0; ks < 4; ++ks) {
        uint32_t af[2][4];
#pragma unroll
        for (int mt = 0; mt < 2; ++mt) {
            int r = wm * 32 + mt * 16 + g4;
            int c = ks * 8 + tig;
            af[mt][0] = As_[r * AST + c];
            af[mt][1] = As_[(r + 8) * AST + c];
            af[mt][2] = As_[r * AST + c + 4];
            af[mt][3] = As_[(r + 8) * AST + c + 4];
        }
#pragma unroll
        for (int nt = 0; nt < 8; ++nt) {
            uint32_t bf[2];
            int n = wn * 64 + nt * 8 + g4;
            bf[0] = Bs_[(ks * 8 + tig) * BST + n];
            bf[1] = Bs_[(ks * 8 + tig + 4) * BST + n];
            mma_tf32(acc[0][nt], af[0], bf);
            mma_tf32(acc[1][nt], af[1], bf);
        }
    }
}

// ---------------- embed GEMM (external fp32 inputs, cvt at store) ------------
__global__ __launch_bounds__(256, 2)
void gemm_tc(const float* __restrict__ A1, const float* __restrict__ W1,
             const float* __restrict__ bias, float* __restrict__ C,
             int M, int K1, int do_relu, int round_out)
{
    __shared__ uint32_t As[BM * AST];
    __shared__ uint32_t Bs[BK * BST];

    const int t    = threadIdx.x;
    const int lane = t & 31;
    const int warp = t >> 5;
    const int wm   = warp & 3;
    const int wn   = warp >> 2;
    const int g4   = lane >> 2;
    const int tig  = lane & 3;
    const int row0 = blockIdx.x * BM;

    float acc[2][8][4];
#pragma unroll
    for (int mt = 0; mt < 2; ++mt)
#pragma unroll
        for (int nt = 0; nt < 8; ++nt)
#pragma unroll
            for (int j = 0; j < 4; ++j) acc[mt][nt][j] = 0.f;

    const int la_m  = t >> 5;
    const int la_k  = lane;
    const int lb_k  = t >> 5;
    const int lb_n4 = lane;

    const float* A = A1;
    const float* W = W1;
    const int    K = K1;
    const int    nk = (K + BK - 1) / BK;

    float  pa[16];
    float4 pb[4];

#pragma unroll
    for (int i = 0; i < 16; ++i) {
        int gm = row0 + la_m + 8 * i, gk = la_k;
        pa[i] = (gm < M && gk < K) ? A[(size_t)gm * K + gk] : 0.f;
    }
#pragma unroll
    for (int i = 0; i < 4; ++i) {
        int gk = lb_k + 8 * i;
        pb[i] = (gk < K)
            ? reinterpret_cast<const float4*>(W + (size_t)gk * BN)[lb_n4]
            : make_float4(0.f, 0.f, 0.f, 0.f);
    }

    for (int it = 0; it < nk; ++it) {
#pragma unroll
        for (int i = 0; i < 16; ++i)
            As[(la_m + 8 * i) * AST + la_k] = f2tf32(pa[i]);
#pragma unroll
        for (int i = 0; i < 4; ++i) {
            uint4 v;
            v.x = f2tf32(pb[i].x); v.y = f2tf32(pb[i].y);
            v.z = f2tf32(pb[i].z); v.w = f2tf32(pb[i].w);
            reinterpret_cast<uint4*>(&Bs[(lb_k + 8 * i) * BST])[lb_n4] = v;
        }
        __syncthreads();

        if (it + 1 < nk) {
            const int k0 = (it + 1) * BK;
#pragma unroll
            for (int i = 0; i < 16; ++i) {
                int gm = row0 + la_m + 8 * i, gk = k0 + la_k;
                pa[i] = (gm < M && gk < K) ? A[(size_t)gm * K + gk] : 0.f;
            }
#pragma unroll
            for (int i = 0; i < 4; ++i) {
                int gk = k0 + lb_k + 8 * i;
                pb[i] = (gk < K)
                    ? reinterpret_cast<const float4*>(W + (size_t)gk * BN)[lb_n4]
                    : make_float4(0.f, 0.f, 0.f, 0.f);
            }
        }

        compute_tile(As, Bs, acc, wm, wn, g4, tig);
        __syncthreads();
    }

#pragma unroll
    for (int mt = 0; mt < 2; ++mt) {
        int r0 = row0 + wm * 32 + mt * 16 + g4;
#pragma unroll
        for (int nt = 0; nt < 8; ++nt) {
            int ccol = wn * 64 + nt * 8 + 2 * tig;
            float b0 = bias[ccol], b1 = bias[ccol + 1];
            float v0 = acc[mt][nt][0] + b0;
            float v1 = acc[mt][nt][1] + b1;
            float v2 = acc[mt][nt][2] + b0;
            float v3 = acc[mt][nt][3] + b1;
            if (do_relu) {
                v0 = fmaxf(v0, 0.f); v1 = fmaxf(v1, 0.f);
                v2 = fmaxf(v2, 0.f); v3 = fmaxf(v3, 0.f);
            }
            if (round_out) {
                v0 = f2tf32f(v0); v1 = f2tf32f(v1);
                v2 = f2tf32f(v2); v3 = f2tf32f(v3);
            }
            if (r0 < M)
                *reinterpret_cast<float2*>(C + (size_t)r0 * BN + ccol) =
                    make_float2(v0, v1);
            if (r0 + 8 < M)
                *reinterpret_cast<float2*>(C + (size_t)(r0 + 8) * BN + ccol) =
                    make_float2(v2, v3);
        }
    }
}

// ---------------- layer GEMM: pre-rounded inputs, cp.async double-buffer -----
// C = A1@W1 + A2@W2 + bias; K1=K2=128 fixed; A1/A2 padded (safe OOB reads).
__device__ __forceinline__ void issue_tile(const float* __restrict__ A1,
                                           const float* __restrict__ W1,
                                           const float* __restrict__ A2,
                                           const float* __restrict__ W2,
                                           uint32_t* __restrict__ Asb,
                                           uint32_t* __restrict__ Bsb,
                                           int it, int row0, int t) {
    const float* Ap = (it < 4) ? A1 : A2;
    const float* Wp = (it < 4) ? W1 : W2;
    const int k0 = (it & 3) * BK;
#pragma unroll
    for (int i = 0; i < 4; ++i) {
        int ch = t + 256 * i;
        int m = ch >> 3, jc = ch & 7;
        cp16(&Asb[m * AST + jc * 4],
             Ap + (size_t)(row0 + m) * 128 + k0 + jc * 4);
    }
#pragma unroll
    for (int i = 0; i < 4; ++i) {
        int ch = t + 256 * i;
        int k = ch >> 5, jn = ch & 31;
        cp16(&Bsb[k * BST + jn * 4],
             Wp + (size_t)(k0 + k) * 128 + jn * 4);
    }
    asm volatile("cp.async.commit_group;\n" ::: "memory");
}

__global__ __launch_bounds__(256, 3)
void gemm_layer(const float* __restrict__ A1, const float* __restrict__ W1,
                const float* __restrict__ A2, const float* __restrict__ W2,
                const float* __restrict__ bias, float* __restrict__ C,
                int M, int do_relu, int round_out)
{
    extern __shared__ char smem[];
    uint32_t* As = reinterpret_cast<uint32_t*>(smem);              // 2 x BM*AST
    uint32_t* Bs = As + 2 * BM * AST;                              // 2 x BK*BST

    const int t    = threadIdx.x;
    const int lane = t & 31;
    const int warp = t >> 5;
    const int wm   = warp & 3;
    const int wn   = warp >> 2;
    const int g4   = lane >> 2;
    const int tig  = lane & 3;
    const int row0 = blockIdx.x * BM;

    float acc[2][8][4];
#pragma unroll
    for (int mt = 0; mt < 2; ++mt)
#pragma unroll
        for (int nt = 0; nt < 8; ++nt)
#pragma unroll
            for (int j = 0; j < 4; ++j) acc[mt][nt][j] = 0.f;

    issue_tile(A1, W1, A2, W2, As, Bs, 0, row0, t);

#pragma unroll 1
    for (int it = 0; it < 8; ++it) {
        const int buf = it & 1;
        if (it < 7) {
            issue_tile(A1, W1, A2, W2,
                       As + (buf ^ 1) * BM * AST, Bs + (buf ^ 1) * BK * BST,
                       it + 1, row0, t);
            asm volatile("cp.async.wait_group 1;\n" ::: "memory");
        } else {
            asm volatile("cp.async.wait_group 0;\n" ::: "memory");
        }
        __syncthreads();
        compute_tile(As + buf * BM * AST, Bs + buf * BK * BST,
                     acc, wm, wn, g4, tig);
        __syncthreads();
    }

#pragma unroll
    for (int mt = 0; mt < 2; ++mt) {
        int r0 = row0 + wm * 32 + mt * 16 + g4;
#pragma unroll
        for (int nt = 0; nt < 8; ++nt) {
            int ccol = wn * 64 + nt * 8 + 2 * tig;
            float b0 = bias[ccol], b1 = bias[ccol + 1];
            float v0 = acc[mt][nt][0] + b0;
            float v1 = acc[mt][nt][1] + b1;
            float v2 = acc[mt][nt][2] + b0;
            float v3 = acc[mt][nt][3] + b1;
            if (do_relu) {
                v0 = fmaxf(v0, 0.f); v1 = fmaxf(v1, 0.f);
                v2 = fmaxf(v2, 0.f); v3 = fmaxf(v3, 0.f);
            }
            if (round_out) {
                v0 = f2tf32f(v0); v1 = f2tf32f(v1);
                v2 = f2tf32f(v2); v3 = f2tf32f(v3);
            }
            if (r0 < M)
                *reinterpret_cast<float2*>(C + (size_t)r0 * BN + ccol) =
                    make_float2(v0, v1);
            if (r0 + 8 < M)
                *reinterpret_cast<float2*>(C + (size_t)(r0 + 8) * BN + ccol) =
                    make_float2(v2, v3);
        }
    }
}

// ---------------- launch ----------------------------------------------------
extern "C" void kernel_launch(void* const* d_in, const int* in_sizes, int n_in,
                              void* d_out, int out_size) {
    const float* d_feat = (const float*)d_in[0];
    const float* m_feat = (const float*)d_in[1];
    const int*   src    = (const int*)  d_in[2];
    const int*   dst    = (const int*)  d_in[3];
    const float* W_d    = (const float*)d_in[4];
    const float* b_d    = (const float*)d_in[5];
    const float* W_m    = (const float*)d_in[6];
    const float* b_m    = (const float*)d_in[7];
    const float* W_s1   = (const float*)d_in[8];
    const float* W_n1   = (const float*)d_in[9];
    const float* b1     = (const float*)d_in[10];
    const float* W_s2   = (const float*)d_in[11];
    const float* W_n2   = (const float*)d_in[12];
    const float* b2     = (const float*)d_in[13];
    float* out = (float*)d_out;

    float *h, *h1, *agg, *wl;
    cudaGetSymbolAddress((void**)&h,   g_h);
    cudaGetSymbolAddress((void**)&h1,  g_h1);
    cudaGetSymbolAddress((void**)&agg, g_agg);
    cudaGetSymbolAddress((void**)&wl,  g_wl);

    const int LAYER_SMEM = (2 * BM * AST + 2 * BK * BST) * 4;   // 71680 B
    static int smem_set = 0;
    if (!smem_set) {
        cudaFuncSetAttribute(gemm_layer,
                             cudaFuncAttributeMaxDynamicSharedMemorySize,
                             LAYER_SMEM);
        smem_set = 1;
    }

    const int grid_embed  = (N_DIS + BM - 1) / BM;    // 196
    const int grid_layer  = (NN    + BM - 1) / BM;    // 391
    const int grid_edges  = (EE + 255) / 256;         // 2344
    const int grid_nodes  = (NN + 255) / 256;         // 196
    const int grid_gather = (NN * 32 + 255) / 256;    // 6250

    // ---- CSR build (also yields inv_deg)
    zero_cnt_kernel<<<grid_nodes, 256>>>();
    count_kernel<<<grid_edges, 256>>>(dst);
    scan1_kernel<<<NB_SCAN, 256>>>();
    scan23_kernel<<<grid_nodes, 256>>>();
    fill_kernel<<<grid_edges, 256>>>(src, dst);

    // ---- pre-round layer weights to tf32
    cvtw_kernel<<<64, 256>>>(W_s1, W_n1, W_s2, W_n2);

    // ---- layer-0 embeddings (tf32-rounded outputs)
    gemm_tc<<<grid_embed, 256>>>(d_feat, W_d, b_d, h, N_DIS, 383, 0, 1);
    gemm_tc<<<grid_embed, 256>>>(m_feat, W_m, b_m,
                                 h + (size_t)N_DIS * EMB, N_MIR, 495, 0, 1);

    // ---- layer 1: h1 = relu(h@Ws1 + agg@Wn1 + b1), rounded
    gather_kernel<<<grid_gather, 256>>>(h);
    gemm_layer<<<grid_layer, 256, LAYER_SMEM>>>(h, wl, agg, wl + 16384,
                                                b1, h1, NN, 1, 1);

    // ---- layer 2: out = h1@Ws2 + agg2@Wn2 + b2 (full fp32 store)
    gather_kernel<<<grid_gather, 256>>>(h1);
    gemm_layer<<<grid_layer, 256, LAYER_SMEM>>>(h1, wl + 2 * 16384,
                                                agg, wl + 3 * 16384,
                                                b2, out, NN, 0, 0);
}

// round 10
// speedup vs baseline: 1.0916x; 1.0916x over previous
#include <cuda_runtime.h>
#include <cstdint>

#define N_DIS 25000
#define N_MIR 25000
#define NN    50000
#define EE    600000
#define EMB   128
#define NB_SCAN 196   // ceil(50000/256)

#define BM 128
#define BN 128
#define BK 32
#define AST 36
#define BST 136

// ---------------- scratch (static device globals: no allocs allowed) --------
// h/h1/agg padded by one M-tile so unguarded cp.async tile reads stay in-bounds.
__device__ float g_h   [(size_t)(NN + BM) * EMB];
__device__ float g_h1  [(size_t)(NN + BM) * EMB];
__device__ float g_agg [(size_t)(NN + BM) * EMB];
__device__ float g_inv [NN];
__device__ int   g_cnt [NN];
__device__ int   g_off [NN];
__device__ int   g_cur [NN];
__device__ int   g_esrc[EE];
__device__ int   g_bsum[NB_SCAN];
__device__ float g_wl  [4 * 128 * 128];   // tf32-rounded layer weights

// ---------------- helpers ----------------------------------------------------
__device__ __forceinline__ uint32_t f2tf32(float x) {
    uint32_t r;
    asm("cvt.rna.tf32.f32 %0, %1;\n" : "=r"(r) : "f"(x));
    return r;
}
__device__ __forceinline__ float f2tf32f(float x) {
    return __uint_as_float(f2tf32(x));
}
__device__ __forceinline__ void mma_tf32(float* d, const uint32_t* a,
                                         const uint32_t* b) {
    asm volatile(
        "mma.sync.aligned.m16n8k8.row.col.f32.tf32.tf32.f32 "
        "{%0,%1,%2,%3},{%4,%5,%6,%7},{%8,%9},{%0,%1,%2,%3};\n"
        : "+f"(d[0]), "+f"(d[1]), "+f"(d[2]), "+f"(d[3])
        : "r"(a[0]), "r"(a[1]), "r"(a[2]), "r"(a[3]), "r"(b[0]), "r"(b[1]));
}
__device__ __forceinline__ void cp16(void* s, const void* g) {
    uint32_t sa = (uint32_t)__cvta_generic_to_shared(s);
    asm volatile("cp.async.cg.shared.global [%0], [%1], 16;\n"
                 :: "r"(sa), "l"(g));
}

// ---------------- CSR build --------------------------------------------------
__global__ void zero_cnt_kernel() {
    int i = blockIdx.x * blockDim.x + threadIdx.x;
    if (i < NN) g_cnt[i] = 0;
}

__global__ void count_kernel(const int* __restrict__ dst) {
    int e = blockIdx.x * blockDim.x + threadIdx.x;
    if (e < EE) atomicAdd(&g_cnt[dst[e]], 1);
}

__global__ void scan1_kernel() {
    __shared__ int sh[256];
    int t = threadIdx.x;
    int i = blockIdx.x * 256 + t;
    int v = (i < NN) ? g_cnt[i] : 0;
    sh[t] = v;
    __syncthreads();
#pragma unroll
    for (int o = 1; o < 256; o <<= 1) {
        int x = (t >= o) ? sh[t - o] : 0;
        __syncthreads();
        sh[t] += x;
        __syncthreads();
    }
    if (i < NN) g_off[i] = sh[t] - v;
    if (t == 255) g_bsum[blockIdx.x] = sh[255];
}

// fused: block b sums g_bsum[0..b-1] itself, then finalizes off/cur/inv
__global__ void scan23_kernel() {
    __shared__ int ws[8];
    int t = threadIdx.x, b = blockIdx.x;
    int v = (t < b && t < NB_SCAN) ? g_bsum[t] : 0;
#pragma unroll
    for (int o = 16; o; o >>= 1) v += __shfl_down_sync(0xffffffffu, v, o);
    if ((t & 31) == 0) ws[t >> 5] = v;
    __syncthreads();
    if (t == 0) {
        int tot = 0;
#pragma unroll
        for (int j = 0; j < 8; ++j) tot += ws[j];
        ws[0] = tot;
    }
    __syncthreads();
    int base = ws[0];
    int i = b * 256 + t;
    if (i < NN) {
        int off = g_off[i] + base;
        g_off[i] = off;
        g_cur[i] = off;
        g_inv[i] = 1.0f / fmaxf((float)g_cnt[i], 1.0f);
    }
}

__global__ void fill_kernel(const int* __restrict__ src,
                            const int* __restrict__ dst) {
    int e = blockIdx.x * blockDim.x + threadIdx.x;
    if (e >= EE) return;
    int d = dst[e];
    int pos = atomicAdd(&g_cur[d], 1);
    g_esrc[pos] = src[e];
}

// ---------------- weight pre-round (tf32) ------------------------------------
__global__ void cvtw_kernel(const float* __restrict__ W_s1,
                            const float* __restrict__ W_n1,
                            const float* __restrict__ W_s2,
                            const float* __restrict__ W_n2) {
    int i = blockIdx.x * 256 + threadIdx.x;
    if (i >= 16384) return;
    g_wl[i]             = f2tf32f(W_s1[i]);
    g_wl[16384 + i]     = f2tf32f(W_n1[i]);
    g_wl[2 * 16384 + i] = f2tf32f(W_s2[i]);
    g_wl[3 * 16384 + i] = f2tf32f(W_n2[i]);
}

// ---------------- gather-mean (stores tf32-rounded) --------------------------
__global__ void gather_kernel(const float* __restrict__ x) {
    int w    = (blockIdx.x * blockDim.x + threadIdx.x) >> 5;
    int lane = threadIdx.x & 31;
    if (w >= NN) return;
    int beg = g_off[w];
    int end = (w == NN - 1) ? EE : g_off[w + 1];

    float4 acc = make_float4(0.f, 0.f, 0.f, 0.f);
    int e = beg;
    for (; e + 1 < end; e += 2) {
        int s0 = g_esrc[e], s1 = g_esrc[e + 1];
        float4 v0 = reinterpret_cast<const float4*>(x + (size_t)s0 * EMB)[lane];
        float4 v1 = reinterpret_cast<const float4*>(x + (size_t)s1 * EMB)[lane];
        acc.x += v0.x + v1.x; acc.y += v0.y + v1.y;
        acc.z += v0.z + v1.z; acc.w += v0.w + v1.w;
    }
    if (e < end) {
        int s = g_esrc[e];
        float4 v = reinterpret_cast<const float4*>(x + (size_t)s * EMB)[lane];
        acc.x += v.x; acc.y += v.y; acc.z += v.z; acc.w += v.w;
    }
    float iv = g_inv[w];
    float4 o;
    o.x = f2tf32f(acc.x * iv); o.y = f2tf32f(acc.y * iv);
    o.z = f2tf32f(acc.z * iv); o.w = f2tf32f(acc.w * iv);
    reinterpret_cast<float4*>(g_agg + (size_t)w * EMB)[lane] = o;
}

// ---------------- shared fragment compute + epilogue --------------------------
__device__ __forceinline__ void compute_tile(const uint32_t* __restrict__ As_,
                                             const uint32_t* __restrict__ Bs_,
                                             float acc[2][8][4],
                                             int wm, int wn, int g4, int tig) {
#pragma unroll
    for (int ks = 0; ks < 4; ++ks) {
        uint32_t af[2][4];
#pragma unroll
        for (int mt = 0; mt < 2; ++mt) {
            int r = wm * 32 + mt * 16 + g4;
            int c = ks * 8 + tig;
            af[mt][0] = As_[r * AST + c];
            af[mt][1] = As_[(r + 8) * AST + c];
            af[mt][2] = As_[r * AST + c + 4];
            af[mt][3] = As_[(r + 8) * AST + c + 4];
        }
#pragma unroll
        for (int nt = 0; nt < 8; ++nt) {
            uint32_t bf[2];
            int n = wn * 64 + nt * 8 + g4;
            bf[0] = Bs_[(ks * 8 + tig) * BST + n];
            bf[1] = Bs_[(ks * 8 + tig + 4) * BST + n];
            mma_tf32(acc[0][nt], af[0], bf);
            mma_tf32(acc[1][nt], af[1], bf);
        }
    }
}

__device__ __forceinline__ void epilogue(float acc[2][8][4],
                                         const float* __restrict__ bias,
                                         float* __restrict__ C, int M, int row0,
                                         int wm, int wn, int g4, int tig,
                                         int do_relu, int round_out) {
#pragma unroll
    for (int mt = 0; mt < 2; ++mt) {
        int r0 = row0 + wm * 32 + mt * 16 + g4;
#pragma unroll
        for (int nt = 0; nt < 8; ++nt) {
            int ccol = wn * 64 + nt * 8 + 2 * tig;
            float b0 = bias[ccol], b1 = bias[ccol + 1];
            float v0 = acc[mt][nt][0] + b0;
            float v1 = acc[mt][nt][1] + b1;
            float v2 = acc[mt][nt][2] + b0;
            float v3 = acc[mt][nt][3] + b1;
            if (do_relu) {
                v0 = fmaxf(v0, 0.f); v1 = fmaxf(v1, 0.f);
                v2 = fmaxf(v2, 0.f); v3 = fmaxf(v3, 0.f);
            }
            if (round_out) {
                v0 = f2tf32f(v0); v1 = f2tf32f(v1);
                v2 = f2tf32f(v2); v3 = f2tf32f(v3);
            }
            if (r0 < M)
                *reinterpret_cast<float2*>(C + (size_t)r0 * BN + ccol) =
                    make_float2(v0, v1);
            if (r0 + 8 < M)
                *reinterpret_cast<float2*>(C + (size_t)(r0 + 8) * BN + ccol) =
                    make_float2(v2, v3);
        }
    }
}

// ---------------- embed GEMM: fp32 in, cvt at STS, double buffer, 1 sync -----
__global__ __launch_bounds__(256, 2)
void gemm_embed(const float* __restrict__ A, const float* __restrict__ W,
                const float* __restrict__ bias, float* __restrict__ C,
                int M, int K, int do_relu, int round_out)
{
    extern __shared__ uint32_t smu[];
    uint32_t* As = smu;                 // 2 x BM*AST
    uint32_t* Bs = smu + 2 * BM * AST;  // 2 x BK*BST

    const int t    = threadIdx.x;
    const int lane = t & 31;
    const int warp = t >> 5;
    const int wm   = warp & 3;
    const int wn   = warp >> 2;
    const int g4   = lane >> 2;
    const int tig  = lane & 3;
    const int row0 = blockIdx.x * BM;

    float acc[2][8][4];
#pragma unroll
    for (int mt = 0; mt < 2; ++mt)
#pragma unroll
        for (int nt = 0; nt < 8; ++nt)
#pragma unroll
            for (int j = 0; j < 4; ++j) acc[mt][nt][j] = 0.f;

    const int la_m  = t >> 5;
    const int la_k  = lane;
    const int lb_k  = t >> 5;
    const int lb_n4 = lane;
    const int nk    = (K + BK - 1) / BK;

    float  pa[16];
    float4 pb[4];

#pragma unroll
    for (int i = 0; i < 16; ++i) {
        int gm = row0 + la_m + 8 * i, gk = la_k;
        pa[i] = (gm < M && gk < K) ? A[(size_t)gm * K + gk] : 0.f;
    }
#pragma unroll
    for (int i = 0; i < 4; ++i) {
        int gk = lb_k + 8 * i;
        pb[i] = (gk < K)
            ? reinterpret_cast<const float4*>(W + (size_t)gk * BN)[lb_n4]
            : make_float4(0.f, 0.f, 0.f, 0.f);
    }

#pragma unroll 1
    for (int it = 0; it < nk; ++it) {
        uint32_t* Ab = As + (it & 1) * BM * AST;
        uint32_t* Bb = Bs + (it & 1) * BK * BST;
#pragma unroll
        for (int i = 0; i < 16; ++i)
            Ab[(la_m + 8 * i) * AST + la_k] = f2tf32(pa[i]);
#pragma unroll
        for (int i = 0; i < 4; ++i) {
            uint4 v;
            v.x = f2tf32(pb[i].x); v.y = f2tf32(pb[i].y);
            v.z = f2tf32(pb[i].z); v.w = f2tf32(pb[i].w);
            reinterpret_cast<uint4*>(&Bb[(lb_k + 8 * i) * BST])[lb_n4] = v;
        }
        __syncthreads();              // ONE barrier per tile (double buffered)

        if (it + 1 < nk) {
            const int k0 = (it + 1) * BK;
#pragma unroll
            for (int i = 0; i < 16; ++i) {
                int gm = row0 + la_m + 8 * i, gk = k0 + la_k;
                pa[i] = (gm < M && gk < K) ? A[(size_t)gm * K + gk] : 0.f;
            }
#pragma unroll
            for (int i = 0; i < 4; ++i) {
                int gk = k0 + lb_k + 8 * i;
                pb[i] = (gk < K)
                    ? reinterpret_cast<const float4*>(W + (size_t)gk * BN)[lb_n4]
                    : make_float4(0.f, 0.f, 0.f, 0.f);
            }
        }

        compute_tile(Ab, Bb, acc, wm, wn, g4, tig);
    }

    epilogue(acc, bias, C, M, row0, wm, wn, g4, tig, do_relu, round_out);
}

// ---------------- layer GEMM: pre-rounded inputs, 3-stage cp.async, 1 sync ---
__device__ __forceinline__ void issue_tile(const float* __restrict__ A1,
                                           const float* __restrict__ W1,
                                           const float* __restrict__ A2,
                                           const float* __restrict__ W2,
                                           uint32_t* __restrict__ Asb,
                                           uint32_t* __restrict__ Bsb,
                                           int it, int row0, int t) {
    const float* Ap = (it < 4) ? A1 : A2;
    const float* Wp = (it < 4) ? W1 : W2;
    const int k0 = (it & 3) * BK;
#pragma unroll
    for (int i = 0; i < 4; ++i) {
        int ch = t + 256 * i;
        int m = ch >> 3, jc = ch & 7;
        cp16(&Asb[m * AST + jc * 4],
             Ap + (size_t)(row0 + m) * 128 + k0 + jc * 4);
    }
#pragma unroll
    for (int i = 0; i < 4; ++i) {
        int ch = t + 256 * i;
        int k = ch >> 5, jn = ch & 31;
        cp16(&Bsb[k * BST + jn * 4],
             Wp + (size_t)(k0 + k) * 128 + jn * 4);
    }
    asm volatile("cp.async.commit_group;\n" ::: "memory");
}

__global__ __launch_bounds__(256, 2)
void gemm_layer(const float* __restrict__ A1, const float* __restrict__ W1,
                const float* __restrict__ A2, const float* __restrict__ W2,
                const float* __restrict__ bias, float* __restrict__ C,
                int M, int do_relu, int round_out)
{
    extern __shared__ uint32_t smu[];
    uint32_t* As = smu;                 // 3 x BM*AST
    uint32_t* Bs = smu + 3 * BM * AST;  // 3 x BK*BST

    const int t    = threadIdx.x;
    const int lane = t & 31;
    const int warp = t >> 5;
    const int wm   = warp & 3;
    const int wn   = warp >> 2;
    const int g4   = lane >> 2;
    const int tig  = lane & 3;
    const int row0 = blockIdx.x * BM;

    float acc[2][8][4];
#pragma unroll
    for (int mt = 0; mt < 2; ++mt)
#pragma unroll
        for (int nt = 0; nt < 8; ++nt)
#pragma unroll
            for (int j = 0; j < 4; ++j) acc[mt][nt][j] = 0.f;

    issue_tile(A1, W1, A2, W2, As, Bs, 0, row0, t);
    issue_tile(A1, W1, A2, W2, As + BM * AST, Bs + BK * BST, 1, row0, t);

#pragma unroll 1
    for (int it = 0; it < 8; ++it) {
        const int sb = it - (it >= 3 ? 3 : 0) - (it >= 6 ? 3 : 0);  // it % 3
        if (it + 1 < 8)
            asm volatile("cp.async.wait_group 1;\n" ::: "memory");
        else
            asm volatile("cp.async.wait_group 0;\n" ::: "memory");
        __syncthreads();              // ONE barrier per tile (triple buffered)

        if (it + 2 < 8) {
            int nb = sb + 2; if (nb >= 3) nb -= 3;   // (it+2) % 3
            issue_tile(A1, W1, A2, W2,
                       As + nb * BM * AST, Bs + nb * BK * BST,
                       it + 2, row0, t);
        }
        compute_tile(As + sb * BM * AST, Bs + sb * BK * BST,
                     acc, wm, wn, g4, tig);
    }

    epilogue(acc, bias, C, M, row0, wm, wn, g4, tig, do_relu, round_out);
}

// ---------------- launch ----------------------------------------------------
extern "C" void kernel_launch(void* const* d_in, const int* in_sizes, int n_in,
                              void* d_out, int out_size) {
    const float* d_feat = (const float*)d_in[0];
    const float* m_feat = (const float*)d_in[1];
    const int*   src    = (const int*)  d_in[2];
    const int*   dst    = (const int*)  d_in[3];
    const float* W_d    = (const float*)d_in[4];
    const float* b_d    = (const float*)d_in[5];
    const float* W_m    = (const float*)d_in[6];
    const float* b_m    = (const float*)d_in[7];
    const float* W_s1   = (const float*)d_in[8];
    const float* W_n1   = (const float*)d_in[9];
    const float* b1     = (const float*)d_in[10];
    const float* W_s2   = (const float*)d_in[11];
    const float* W_n2   = (const float*)d_in[12];
    const float* b2     = (const float*)d_in[13];
    float* out = (float*)d_out;

    float *h, *h1, *agg, *wl;
    cudaGetSymbolAddress((void**)&h,   g_h);
    cudaGetSymbolAddress((void**)&h1,  g_h1);
    cudaGetSymbolAddress((void**)&agg, g_agg);
    cudaGetSymbolAddress((void**)&wl,  g_wl);

    const int EMB_SMEM   = (2 * BM * AST + 2 * BK * BST) * 4;   // 71680 B
    const int LAYER_SMEM = (3 * BM * AST + 3 * BK * BST) * 4;   // 107520 B

    static cudaEvent_t ev_fork = nullptr, ev_join = nullptr;
    static int init_done = 0;
    if (!init_done) {
        cudaFuncSetAttribute(gemm_embed,
                             cudaFuncAttributeMaxDynamicSharedMemorySize,
                             EMB_SMEM);
        cudaFuncSetAttribute(gemm_layer,
                             cudaFuncAttributeMaxDynamicSharedMemorySize,
                             LAYER_SMEM);
        cudaEventCreateWithFlags(&ev_fork, cudaEventDisableTiming);
        cudaEventCreateWithFlags(&ev_join, cudaEventDisableTiming);
        init_done = 1;
    }

    cudaStream_t main_s = 0;                   // legacy default (capture stream)
    cudaStream_t aux_s  = cudaStreamPerThread; // second stream, no creation

    const int grid_embed  = (N_DIS + BM - 1) / BM;    // 196
    const int grid_layer  = (NN    + BM - 1) / BM;    // 391
    const int grid_edges  = (EE + 255) / 256;         // 2344
    const int grid_nodes  = (NN + 255) / 256;         // 196
    const int grid_gather = (NN * 32 + 255) / 256;    // 6250

    // ---- fork: CSR build + weight pre-round on aux, embed GEMMs on main ----
    cudaEventRecord(ev_fork, main_s);
    cudaStreamWaitEvent(aux_s, ev_fork, 0);

    gemm_embed<<<grid_embed, 256, EMB_SMEM, main_s>>>(
        d_feat, W_d, b_d, h, N_DIS, 383, 0, 1);                    // launch 1
    zero_cnt_kernel<<<grid_nodes, 256, 0, aux_s>>>();              // launch 2
    count_kernel<<<grid_edges, 256, 0, aux_s>>>(dst);              // launch 3
    gemm_embed<<<grid_embed, 256, EMB_SMEM, main_s>>>(
        m_feat, W_m, b_m, h + (size_t)N_DIS * EMB, N_MIR, 495, 0, 1); // launch 4
    scan1_kernel<<<NB_SCAN, 256, 0, aux_s>>>();
    scan23_kernel<<<grid_nodes, 256, 0, aux_s>>>();
    fill_kernel<<<grid_edges, 256, 0, aux_s>>>(src, dst);
    cvtw_kernel<<<64, 256, 0, aux_s>>>(W_s1, W_n1, W_s2, W_n2);

    cudaEventRecord(ev_join, aux_s);
    cudaStreamWaitEvent(main_s, ev_join, 0);

    // ---- layer 1: h1 = relu(h@Ws1 + agg@Wn1 + b1), rounded
    gather_kernel<<<grid_gather, 256, 0, main_s>>>(h);
    gemm_layer<<<grid_layer, 256, LAYER_SMEM, main_s>>>(
        h, wl, agg, wl + 16384, b1, h1, NN, 1, 1);

    // ---- layer 2: out = h1@Ws2 + agg2@Wn2 + b2 (full fp32 store)
    gather_kernel<<<grid_gather, 256, 0, main_s>>>(h1);
    gemm_layer<<<grid_layer, 256, LAYER_SMEM, main_s>>>(
        h1, wl + 2 * 16384, agg, wl + 3 * 16384, b2, out, NN, 0, 0);
}